// round 4
// baseline (speedup 1.0000x reference)
#include <cuda_runtime.h>
#include <math.h>

#define NN 12288
#define EE 196608
#define FIN 1433

// ---------------- scratch (no allocations allowed) ----------------
__device__ __align__(16) float g_xw[NN * 32];    // x @ W1 (atomic accum)
__device__ __align__(16) float g_hacc[NN * 32];  // GCN accumulation
__device__ __align__(16) float g_h[NN * 32];     // GCN output (post relu)
__device__ __align__(16) float g_agg[NN * 32];   // SAGE sum
__device__ int g_deg[NN];
__device__ int g_cnt[NN];
__device__ int g_is64;
__device__ int g_src[EE];
__device__ int g_dst[EE];

__device__ __forceinline__ int edge_at(const void* ei, int j) {
    if (g_is64) return (int)((const long long*)ei)[j];
    return ((const int*)ei)[j];
}

// f32x2 packed FMA helpers
__device__ __forceinline__ void ffma2(unsigned long long& d,
                                      unsigned long long a,
                                      unsigned long long b) {
    asm("fma.rn.f32x2 %0, %1, %2, %0;" : "+l"(d) : "l"(a), "l"(b));
}
__device__ __forceinline__ float2 unpack2(unsigned long long v) {
    float2 r;
    asm("mov.b64 {%0, %1}, %2;" : "=f"(r.x), "=f"(r.y) : "l"(v));
    return r;
}

// ---------------- K0: zero scratch + dtype detect ----------------
__global__ void k_zero(const int* __restrict__ ei32) {
    int t = blockIdx.x * blockDim.x + threadIdx.x;
    if (t < NN * 32) { g_hacc[t] = 0.f; g_agg[t] = 0.f; g_xw[t] = 0.f; }
    if (t < NN) { g_deg[t] = 0; g_cnt[t] = 0; }
    if (t == 0) {
        int all_zero_high = 1;
        for (int i = 0; i < 64; i++)
            if (ei32[2 * i + 1] != 0) { all_zero_high = 0; break; }
        g_is64 = all_zero_high;
    }
}

// ---------------- K1: degrees + int32 edge cache ----------------
__global__ void k_deg(const void* __restrict__ ei) {
    int e = blockIdx.x * blockDim.x + threadIdx.x;
    if (e >= EE) return;
    int s = edge_at(ei, e);
    int c = edge_at(ei, EE + e);
    g_src[e] = s;
    g_dst[e] = c;
    atomicAdd(&g_deg[c], 1);
    atomicAdd(&g_cnt[s], 1);
}

// ---------------- K2: xw += x @ W1 (K-split, pipelined, f32x2) -------------
// BM=64 rows/block, BK=32, 128 threads. grid = (192, 2); y splits K tiles
// 0..22 / 23..44. Each thread computes 4 rows x 4 cols.
// Row-packed accumulators: acc[rp][c] = f32x2 over rows (r0+2rp, r0+2rp+1).
#define BM 64
#define BK 32
#define NT 45      // ceil(1433/32)
#define NT0 23     // y=0 tile count (k < 736); y=1 handles the FIN tail
__global__ __launch_bounds__(128) void k_gemm(const float* __restrict__ x,
                                              const float* __restrict__ W1) {
    __shared__ __align__(16) float  xs[BK][BM + 4];   // [kk][row]
    __shared__ __align__(16) float2 wd[BK][32];       // duplicated W pairs
    const int tid = threadIdx.x;
    const int tx = tid & 7;        // col group (4 cols)
    const int ty = tid >> 3;       // row group (4 rows), 0..15
    const int lk = tid & 31;       // loader: k lane
    const int lr = tid >> 5;       // loader: row base 0..3
    const int row0 = blockIdx.x * BM;
    const int t0 = (blockIdx.y == 0) ? 0 : NT0;
    const int t1 = (blockIdx.y == 0) ? NT0 : NT;

    unsigned long long acc[2][4];
#pragma unroll
    for (int rp = 0; rp < 2; rp++)
#pragma unroll
        for (int c = 0; c < 4; c++) acc[rp][c] = 0ULL;

    float xr[16], wr[8];

#define LOAD_TILE(T)                                                        \
    {                                                                       \
        int k = (T) * BK + lk;                                              \
        bool kin = (k < FIN);                                               \
        _Pragma("unroll") for (int i = 0; i < 16; i++) {                    \
            int r = lr + i * 4;                                             \
            xr[i] = kin ? x[(row0 + r) * FIN + k] : 0.f;                    \
        }                                                                   \
        _Pragma("unroll") for (int i = 0; i < 8; i++) {                     \
            int idx = tid + i * 128;                                        \
            int kg = (T) * BK + (idx >> 5);                                 \
            wr[i] = (kg < FIN) ? W1[kg * 32 + (idx & 31)] : 0.f;            \
        }                                                                   \
    }

    LOAD_TILE(t0);
    for (int t = t0; t < t1; t++) {
#pragma unroll
        for (int i = 0; i < 16; i++) xs[lk][lr + i * 4] = xr[i];
#pragma unroll
        for (int i = 0; i < 8; i++) {
            int idx = tid + i * 128;
            wd[idx >> 5][idx & 31] = make_float2(wr[i], wr[i]);
        }
        __syncthreads();
        if (t + 1 < t1) LOAD_TILE(t + 1);
#pragma unroll
        for (int kk = 0; kk < BK; kk++) {
            ulonglong2 a  = *reinterpret_cast<const ulonglong2*>(&xs[kk][ty * 4]);
            ulonglong2 b0 = *reinterpret_cast<const ulonglong2*>(&wd[kk][tx * 4]);
            ulonglong2 b1 = *reinterpret_cast<const ulonglong2*>(&wd[kk][tx * 4 + 2]);
            ffma2(acc[0][0], a.x, b0.x); ffma2(acc[0][1], a.x, b0.y);
            ffma2(acc[0][2], a.x, b1.x); ffma2(acc[0][3], a.x, b1.y);
            ffma2(acc[1][0], a.y, b0.x); ffma2(acc[1][1], a.y, b0.y);
            ffma2(acc[1][2], a.y, b1.x); ffma2(acc[1][3], a.y, b1.y);
        }
        __syncthreads();
    }
#pragma unroll
    for (int rp = 0; rp < 2; rp++)
#pragma unroll
        for (int c = 0; c < 4; c++) {
            float2 v = unpack2(acc[rp][c]);
            int r = row0 + ty * 4 + rp * 2;
            int cc = tx * 4 + c;
            atomicAdd(&g_xw[r * 32 + cc], v.x);
            atomicAdd(&g_xw[(r + 1) * 32 + cc], v.y);
        }
}

// ---------------- K3: GCN edge scatter: hacc[r] += dis[r]*dis[c]*xw[c] -----
__global__ void k_gcn_scatter() {
    int t = blockIdx.x * blockDim.x + threadIdx.x;
    int e = t >> 3, q = (t & 7) * 4;
    if (e >= EE) return;
    int r = g_src[e];
    int c = g_dst[e];
    float w = rsqrtf((float)(g_deg[r] + 1) * (float)(g_deg[c] + 1));
    float4 v = *reinterpret_cast<const float4*>(&g_xw[c * 32 + q]);
    float* dst = &g_hacc[r * 32 + q];
    atomicAdd(dst + 0, w * v.x);
    atomicAdd(dst + 1, w * v.y);
    atomicAdd(dst + 2, w * v.z);
    atomicAdd(dst + 3, w * v.w);
}

// ---------------- K4: self loop + bias + relu -> h ----------------
__global__ void k_gcn_finish(const float* __restrict__ b1) {
    int t = blockIdx.x * blockDim.x + threadIdx.x;
    if (t >= NN * 32) return;
    int i = t >> 5, j = t & 31;
    float d2 = 1.0f / (float)(g_deg[i] + 1);
    float v = g_hacc[t] + d2 * g_xw[t] + b1[j];
    g_h[t] = fmaxf(v, 0.f);
}

// ---------------- K5: SAGE scatter: agg[src] += h[dst] ----------------
__global__ void k_sage_scatter() {
    int t = blockIdx.x * blockDim.x + threadIdx.x;
    int e = t >> 3, q = (t & 7) * 4;
    if (e >= EE) return;
    int src = g_src[e];
    int dst = g_dst[e];
    float4 v = *reinterpret_cast<const float4*>(&g_h[dst * 32 + q]);
    float* d = &g_agg[src * 32 + q];
    atomicAdd(d + 0, v.x);
    atomicAdd(d + 1, v.y);
    atomicAdd(d + 2, v.z);
    atomicAdd(d + 3, v.w);
}

// ---------------- K6: head, one warp per node ----------------
__global__ __launch_bounds__(128) void k_head(const float* __restrict__ Wl,
                                              const float* __restrict__ bl,
                                              const float* __restrict__ Wr,
                                              const float* __restrict__ br,
                                              const float* __restrict__ W3,
                                              const float* __restrict__ b3,
                                              float* __restrict__ out) {
    __shared__ float sWl[512], sWr[512], sW3[112], sbl[16], sbr[16], sb3[7];
    int tid = threadIdx.x;
    for (int i = tid; i < 512; i += 128) { sWl[i] = Wl[i]; sWr[i] = Wr[i]; }
    if (tid < 112) sW3[tid] = W3[tid];
    if (tid < 16) { sbl[tid] = bl[tid]; sbr[tid] = br[tid]; }
    if (tid < 7)  sb3[tid] = b3[tid];
    __syncthreads();

    const unsigned FULL = 0xffffffffu;
    int warp = tid >> 5, lane = tid & 31;
    int node = blockIdx.x * 4 + warp;
    if (node >= NN) return;

    float hk = g_h[node * 32 + lane];
    float cn = (float)g_cnt[node];
    float ak = g_agg[node * 32 + lane] * (1.0f / fmaxf(cn, 1.0f));

    int l16 = lane & 15;
    float acc = 0.f;
#pragma unroll
    for (int k = 0; k < 32; k++) {
        float hv = __shfl_sync(FULL, hk, k);
        float av = __shfl_sync(FULL, ak, k);
        acc = fmaf(hv, sWl[k * 16 + l16], acc);
        acc = fmaf(av, sWr[k * 16 + l16], acc);
    }
    float o = fmaxf(acc + sbl[l16] + sbr[l16], 0.f);
    if (lane >= 16) o = 0.f;

    float ss = o * o;
#pragma unroll
    for (int off = 16; off; off >>= 1) ss += __shfl_xor_sync(FULL, ss, off);
    float on = o / (sqrtf(ss) + 1e-6f);

    int c7 = lane < 7 ? lane : 6;
    float lg = 0.f;
#pragma unroll
    for (int k = 0; k < 16; k++) {
        float ov = __shfl_sync(FULL, on, k);
        lg = fmaf(ov, sW3[k * 7 + c7], lg);
    }
    lg += sb3[c7];

    float v = lane < 7 ? lg : -INFINITY;
    float m = v;
#pragma unroll
    for (int off = 4; off; off >>= 1) m = fmaxf(m, __shfl_xor_sync(FULL, m, off));
    float ex = lane < 7 ? expf(lg - m) : 0.f;
    float s = ex;
#pragma unroll
    for (int off = 4; off; off >>= 1) s += __shfl_xor_sync(FULL, s, off);
    if (lane < 7) out[node * 7 + lane] = ex / s;
}

// ---------------- launch ----------------
extern "C" void kernel_launch(void* const* d_in, const int* in_sizes, int n_in,
                              void* d_out, int out_size) {
    const float* x  = (const float*)d_in[0];
    const void*  ei = d_in[1];
    const float* W1 = (const float*)d_in[2];
    const float* b1 = (const float*)d_in[3];
    const float* Wl = (const float*)d_in[4];
    const float* bl = (const float*)d_in[5];
    const float* Wr = (const float*)d_in[6];
    const float* br = (const float*)d_in[7];
    const float* W3 = (const float*)d_in[8];
    const float* b3 = (const float*)d_in[9];
    float* out = (float*)d_out;

    k_zero<<<(NN * 32 + 255) / 256, 256>>>((const int*)ei);
    k_deg<<<(EE + 255) / 256, 256>>>(ei);
    dim3 ggrid(NN / BM, 2);
    k_gemm<<<ggrid, 128>>>(x, W1);
    k_gcn_scatter<<<(EE * 8 + 255) / 256, 256>>>();
    k_gcn_finish<<<(NN * 32 + 255) / 256, 256>>>(b1);
    k_sage_scatter<<<(EE * 8 + 255) / 256, 256>>>();
    k_head<<<NN / 4, 128>>>(Wl, bl, Wr, br, W3, b3, out);
}

// round 5
// speedup vs baseline: 1.5576x; 1.5576x over previous
#include <cuda_runtime.h>
#include <math.h>

#define NN 12288
#define EE 196608
#define FIN 1433

// ---------------- scratch (no allocations allowed) ----------------
__device__ __align__(16) float g_xw[NN * 32];    // x @ W1 (atomic accum)
__device__ __align__(16) float g_hacc[NN * 32];  // GCN accumulation
__device__ __align__(16) float g_h[NN * 32];     // GCN output (post relu)
__device__ __align__(16) float g_agg[NN * 32];   // SAGE sum
__device__ int   g_deg[NN];
__device__ int   g_cnt[NN];
__device__ float g_dis[NN];
__device__ int   g_is64;
__device__ int   g_src[EE];   // int32 edge cache
__device__ int   g_dst[EE];

__device__ __forceinline__ int edge_at(const void* ei, int j) {
    if (g_is64) return (int)((const long long*)ei)[j];
    return ((const int*)ei)[j];
}

// f32x2 packed FMA helpers
__device__ __forceinline__ void ffma2(unsigned long long& d,
                                      unsigned long long a,
                                      unsigned long long b) {
    asm("fma.rn.f32x2 %0, %1, %2, %0;" : "+l"(d) : "l"(a), "l"(b));
}
__device__ __forceinline__ unsigned long long dup2(float v) {
    unsigned long long r;
    asm("mov.b64 %0, {%1, %1};" : "=l"(r) : "f"(v));
    return r;
}
__device__ __forceinline__ float2 unpack2(unsigned long long v) {
    float2 r;
    asm("mov.b64 {%0, %1}, %2;" : "=f"(r.x), "=f"(r.y) : "l"(v));
    return r;
}

// ---------------- K0: zero scratch + dtype detect ----------------
__global__ void k_zero(const int* __restrict__ ei32) {
    int t = blockIdx.x * blockDim.x + threadIdx.x;
    if (t < NN * 32) { g_hacc[t] = 0.f; g_agg[t] = 0.f; g_xw[t] = 0.f; }
    if (t < NN) { g_deg[t] = 0; g_cnt[t] = 0; }
    if (t == 0) {
        int all_zero_high = 1;
        for (int i = 0; i < 64; i++)
            if (ei32[2 * i + 1] != 0) { all_zero_high = 0; break; }
        g_is64 = all_zero_high;
    }
}

// ---------------- K1: degrees + int32 edge cache ----------------
__global__ void k_deg(const void* __restrict__ ei) {
    int e = blockIdx.x * blockDim.x + threadIdx.x;
    if (e >= EE) return;
    int s = edge_at(ei, e);
    int c = edge_at(ei, EE + e);
    g_src[e] = s;
    g_dst[e] = c;
    atomicAdd(&g_deg[c], 1);
    atomicAdd(&g_cnt[s], 1);
}

// ---------------- K2: dis = (deg+1)^-1/2 ----------------
__global__ void k_dis() {
    int i = blockIdx.x * blockDim.x + threadIdx.x;
    if (i >= NN) return;
    g_dis[i] = 1.0f / sqrtf((float)(g_deg[i] + 1));
}

// ---------------- K3: xw += x @ W1 via packed f32x2 FMA (3-way K split) ----
// Exactly the round-3 inner kernel (BM=32, 64 threads, 4x4 per thread),
// with blockIdx.y splitting the 45 K-tiles into 15/15/15.
#define BM 32
#define BK 32
#define NT 45        // ceil(1433/32)
#define KSPLIT 3
#define TPS 15       // tiles per split
__global__ __launch_bounds__(64) void k_gemm(const float* __restrict__ x,
                                             const float* __restrict__ W1) {
    __shared__ float xs[BK][BM + 4];   // [kk][row]
    __shared__ float ws[BK][32];
    const int tid = threadIdx.x;
    const int tx = tid & 7;      // col group (4 cols)
    const int ty = tid >> 3;     // row group (4 rows), 0..7
    const int row0 = blockIdx.x * BM;
    const int lk = tid & 31;
    const int lr = tid >> 5;     // 0..1
    const int t0 = blockIdx.y * TPS;
    const int t1 = t0 + TPS;     // 3*15 = 45 = NT exactly

    unsigned long long acc[4][2];
#pragma unroll
    for (int r = 0; r < 4; r++)
#pragma unroll
        for (int c = 0; c < 2; c++) acc[r][c] = 0ULL;

    for (int t = t0; t < t1; t++) {
        int k0 = t * BK;
        int k = k0 + lk;
        bool kin = (k < FIN);
#pragma unroll
        for (int i = 0; i < 16; i++) {
            int r = lr + i * 2;
            xs[lk][r] = kin ? x[(row0 + r) * FIN + k] : 0.f;
        }
#pragma unroll
        for (int i = 0; i < 16; i++) {
            int idx = tid + i * 64;
            int kk = idx >> 5, c = idx & 31;
            ws[kk][c] = (k0 + kk < FIN) ? W1[(k0 + kk) * 32 + c] : 0.f;
        }
        __syncthreads();
#pragma unroll
        for (int kk = 0; kk < BK; kk++) {
            float4 a = *reinterpret_cast<const float4*>(&xs[kk][ty * 4]);
            ulonglong2 b = *reinterpret_cast<const ulonglong2*>(&ws[kk][tx * 4]);
            unsigned long long a0 = dup2(a.x), a1 = dup2(a.y);
            unsigned long long a2 = dup2(a.z), a3 = dup2(a.w);
            ffma2(acc[0][0], a0, b.x); ffma2(acc[0][1], a0, b.y);
            ffma2(acc[1][0], a1, b.x); ffma2(acc[1][1], a1, b.y);
            ffma2(acc[2][0], a2, b.x); ffma2(acc[2][1], a2, b.y);
            ffma2(acc[3][0], a3, b.x); ffma2(acc[3][1], a3, b.y);
        }
        __syncthreads();
    }
#pragma unroll
    for (int r = 0; r < 4; r++) {
        float2 lo = unpack2(acc[r][0]);
        float2 hi = unpack2(acc[r][1]);
        float* dst = &g_xw[(row0 + ty * 4 + r) * 32 + tx * 4];
        atomicAdd(dst + 0, lo.x);
        atomicAdd(dst + 1, lo.y);
        atomicAdd(dst + 2, hi.x);
        atomicAdd(dst + 3, hi.y);
    }
}

// ---------------- K4: GCN edge scatter: hacc[r] += dis[r]*dis[c]*xw[c] ------
__global__ void k_gcn_scatter() {
    int t = blockIdx.x * blockDim.x + threadIdx.x;
    int e = t >> 3, q = (t & 7) * 4;
    if (e >= EE) return;
    int r = g_src[e];
    int c = g_dst[e];
    float w = g_dis[r] * g_dis[c];
    float4 v = *reinterpret_cast<const float4*>(&g_xw[c * 32 + q]);
    float* dst = &g_hacc[r * 32 + q];
    atomicAdd(dst + 0, w * v.x);
    atomicAdd(dst + 1, w * v.y);
    atomicAdd(dst + 2, w * v.z);
    atomicAdd(dst + 3, w * v.w);
}

// ---------------- K5: self loop + bias + relu -> h ----------------
__global__ void k_gcn_finish(const float* __restrict__ b1) {
    int t = blockIdx.x * blockDim.x + threadIdx.x;
    if (t >= NN * 32) return;
    int i = t >> 5, j = t & 31;
    float d = g_dis[i];
    float v = g_hacc[t] + d * d * g_xw[t] + b1[j];
    g_h[t] = fmaxf(v, 0.f);
}

// ---------------- K6: SAGE scatter: agg[src] += h[dst] ----------------
__global__ void k_sage_scatter() {
    int t = blockIdx.x * blockDim.x + threadIdx.x;
    int e = t >> 3, q = (t & 7) * 4;
    if (e >= EE) return;
    int src = g_src[e];
    int dst = g_dst[e];
    float4 v = *reinterpret_cast<const float4*>(&g_h[dst * 32 + q]);
    float* d = &g_agg[src * 32 + q];
    atomicAdd(d + 0, v.x);
    atomicAdd(d + 1, v.y);
    atomicAdd(d + 2, v.z);
    atomicAdd(d + 3, v.w);
}

// ---------------- K7: head, one warp per node ----------------
__global__ __launch_bounds__(128) void k_head(const float* __restrict__ Wl,
                                              const float* __restrict__ bl,
                                              const float* __restrict__ Wr,
                                              const float* __restrict__ br,
                                              const float* __restrict__ W3,
                                              const float* __restrict__ b3,
                                              float* __restrict__ out) {
    __shared__ float sWl[512], sWr[512], sW3[112], sbl[16], sbr[16], sb3[7];
    int tid = threadIdx.x;
    for (int i = tid; i < 512; i += 128) { sWl[i] = Wl[i]; sWr[i] = Wr[i]; }
    if (tid < 112) sW3[tid] = W3[tid];
    if (tid < 16) { sbl[tid] = bl[tid]; sbr[tid] = br[tid]; }
    if (tid < 7)  sb3[tid] = b3[tid];
    __syncthreads();

    const unsigned FULL = 0xffffffffu;
    int warp = tid >> 5, lane = tid & 31;
    int node = blockIdx.x * 4 + warp;
    if (node >= NN) return;

    float hk = g_h[node * 32 + lane];
    float cn = (float)g_cnt[node];
    float ak = g_agg[node * 32 + lane] * (1.0f / fmaxf(cn, 1.0f));

    int l16 = lane & 15;
    float acc = 0.f;
#pragma unroll
    for (int k = 0; k < 32; k++) {
        float hv = __shfl_sync(FULL, hk, k);
        float av = __shfl_sync(FULL, ak, k);
        acc = fmaf(hv, sWl[k * 16 + l16], acc);
        acc = fmaf(av, sWr[k * 16 + l16], acc);
    }
    float o = fmaxf(acc + sbl[l16] + sbr[l16], 0.f);
    if (lane >= 16) o = 0.f;

    float ss = o * o;
#pragma unroll
    for (int off = 16; off; off >>= 1) ss += __shfl_xor_sync(FULL, ss, off);
    float on = o / (sqrtf(ss) + 1e-6f);

    int c7 = lane < 7 ? lane : 6;
    float lg = 0.f;
#pragma unroll
    for (int k = 0; k < 16; k++) {
        float ov = __shfl_sync(FULL, on, k);
        lg = fmaf(ov, sW3[k * 7 + c7], lg);
    }
    lg += sb3[c7];

    float v = lane < 7 ? lg : -INFINITY;
    float m = v;
#pragma unroll
    for (int off = 4; off; off >>= 1) m = fmaxf(m, __shfl_xor_sync(FULL, m, off));
    float ex = lane < 7 ? expf(lg - m) : 0.f;
    float s = ex;
#pragma unroll
    for (int off = 4; off; off >>= 1) s += __shfl_xor_sync(FULL, s, off);
    if (lane < 7) out[node * 7 + lane] = ex / s;
}

// ---------------- launch ----------------
extern "C" void kernel_launch(void* const* d_in, const int* in_sizes, int n_in,
                              void* d_out, int out_size) {
    const float* x  = (const float*)d_in[0];
    const void*  ei = d_in[1];
    const float* W1 = (const float*)d_in[2];
    const float* b1 = (const float*)d_in[3];
    const float* Wl = (const float*)d_in[4];
    const float* bl = (const float*)d_in[5];
    const float* Wr = (const float*)d_in[6];
    const float* br = (const float*)d_in[7];
    const float* W3 = (const float*)d_in[8];
    const float* b3 = (const float*)d_in[9];
    float* out = (float*)d_out;

    k_zero<<<(NN * 32 + 255) / 256, 256>>>((const int*)ei);
    k_deg<<<(EE + 255) / 256, 256>>>(ei);
    k_dis<<<(NN + 255) / 256, 256>>>();
    dim3 ggrid(NN / BM, KSPLIT);
    k_gemm<<<ggrid, 64>>>(x, W1);
    k_gcn_scatter<<<(EE * 8 + 255) / 256, 256>>>();
    k_gcn_finish<<<(NN * 32 + 255) / 256, 256>>>(b1);
    k_sage_scatter<<<(EE * 8 + 255) / 256, 256>>>();
    k_head<<<NN / 4, 128>>>(Wl, bl, Wr, br, W3, b3, out);
}